// round 10
// baseline (speedup 1.0000x reference)
#include <cuda_runtime.h>
#include <cstdint>

#define NXX 128
#define VOL (128*128*128)
#define NB  2
#define NR  3
#define LAMBDA 1e-3f
#define EPSI   1e-12f
#define NITER  10
#define INV128f 0.0078125f
#define PLANE_SMEM 131072   // 16384 float2
#define PTHREADS 640        // 20 warps

// ---------------------------------------------------------------------------
// Buffers. CG vectors packed float2 (x=batch0, y=batch1), natural [x][y][z].
// C0/tmp transposed [zp][x][y] (y contig). Se permuted [zp][yp][xp].
// d_part: pAp partials (512/batch). d_rsp: rs partials, parity-buffered.
// ---------------------------------------------------------------------------
static __device__ float2 d_C0 [VOL];
static __device__ float2 d_tmp[NR*VOL];
static __device__ float  d_Se [NR*VOL];
static __device__ uchar2 d_m8 [NR*VOL];
static __device__ float2 d_bb [VOL];
static __device__ float2 d_xk [VOL];
static __device__ float2 d_rr [VOL];
static __device__ float2 d_pp [VOL];
static __device__ float2 d_Ap [VOL];
static __device__ float2 d_W  [NXX];
static __device__ float  d_part[NB*1024];
static __device__ float  d_rsp [2*NB*256];   // [parity][batch][256]

__device__ __forceinline__ float2 c_add(float2 a, float2 b){ return make_float2(a.x+b.x, a.y+b.y); }
__device__ __forceinline__ float2 c_sub(float2 a, float2 b){ return make_float2(a.x-b.x, a.y-b.y); }
__device__ __forceinline__ float2 c_mul(float2 a, float2 b){ return make_float2(a.x*b.x-a.y*b.y, a.x*b.y+a.y*b.x); }
__device__ __forceinline__ float2 c_mulc(float2 a, float2 w){ return make_float2(a.x*w.x+a.y*w.y, a.y*w.x-a.x*w.y); }

// XOR-swizzled smem indexing (conflict-free in both transpose directions)
__device__ __forceinline__ int swz32 (int row, int col){ return (row<<5) + (col ^ (row&31)); }   // [128][32]
__device__ __forceinline__ int swz128(int row, int col){ return (row<<7) + (col ^ (row&31)); }   // [128][128]

// per-lane register twiddles (kernel-invariant)
struct Tw { float2 s16,s8,s4,s2,f1,f2,f3; };
__device__ __forceinline__ Tw load_tw(int l){
  Tw t;
  t.s16=d_W[(l&15)<<2]; t.s8=d_W[(l&7)<<3]; t.s4=d_W[(l&3)<<4]; t.s2=d_W[(l&1)<<5];
  t.f1=d_W[l]; t.f2=d_W[2*l]; t.f3=d_W[3*l];
  return t;
}

__device__ __forceinline__ void fstage(float2 v[4], int l, int d, float2 w){
  bool up = (l & d) != 0;
  #pragma unroll
  for (int k=0;k<4;k++){
    float2 p;
    p.x=__shfl_xor_sync(0xffffffffu, v[k].x, d);
    p.y=__shfl_xor_sync(0xffffffffu, v[k].y, d);
    v[k] = up ? c_mul(c_sub(p, v[k]), w) : c_add(v[k], p);
  }
}
__device__ __forceinline__ void fstage1(float2 v[4], int l){
  bool up = (l & 1) != 0;
  #pragma unroll
  for (int k=0;k<4;k++){
    float2 p;
    p.x=__shfl_xor_sync(0xffffffffu, v[k].x, 1);
    p.y=__shfl_xor_sync(0xffffffffu, v[k].y, 1);
    v[k] = up ? c_sub(p, v[k]) : c_add(v[k], p);
  }
}
__device__ __forceinline__ void istage(float2 v[4], int l, int d, float2 w){
  bool up = (l & d) != 0;
  #pragma unroll
  for (int k=0;k<4;k++){
    float2 own = up ? c_mulc(v[k], w) : v[k];
    float2 p;
    p.x=__shfl_xor_sync(0xffffffffu, own.x, d);
    p.y=__shfl_xor_sync(0xffffffffu, own.y, d);
    v[k] = up ? c_sub(p, own) : c_add(own, p);
  }
}
__device__ __forceinline__ void istage1(float2 v[4], int l){
  bool up = (l & 1) != 0;
  #pragma unroll
  for (int k=0;k<4;k++){
    float2 p;
    p.x=__shfl_xor_sync(0xffffffffu, v[k].x, 1);
    p.y=__shfl_xor_sync(0xffffffffu, v[k].y, 1);
    v[k] = up ? c_sub(p, v[k]) : c_add(v[k], p);
  }
}

// Warp 128-pt FFT. Lane l, reg k holds x[l+32k] (natural) on forward input.
// Forward output: position p=l+32k holds X[k(p)], k(p)=(p>>5)+4*bitrev5(p&31).
// Inverse consumes that layout, returns natural order scaled 1/128.
__device__ __forceinline__ void wf_fwd(float2 v[4], const Tw& t, int l){
  float2 t0=c_add(v[0],v[2]), t1=c_sub(v[0],v[2]);
  float2 t2=c_add(v[1],v[3]), t3=c_sub(v[1],v[3]);
  float2 mi3 = make_float2(t3.y,-t3.x);
  v[0]=c_add(t0,t2); v[2]=c_sub(t0,t2);
  v[1]=c_add(t1,mi3); v[3]=c_sub(t1,mi3);
  v[1]=c_mul(v[1], t.f1);
  v[2]=c_mul(v[2], t.f2);
  v[3]=c_mul(v[3], t.f3);
  fstage(v,l,16,t.s16);
  fstage(v,l,8, t.s8);
  fstage(v,l,4, t.s4);
  fstage(v,l,2, t.s2);
  fstage1(v,l);
}
__device__ __forceinline__ void wf_inv(float2 v[4], const Tw& t, int l){
  istage1(v,l);
  istage(v,l,2, t.s2);
  istage(v,l,4, t.s4);
  istage(v,l,8, t.s8);
  istage(v,l,16,t.s16);
  float2 a1=c_mulc(v[1],t.f1), a2=c_mulc(v[2],t.f2), a3=c_mulc(v[3],t.f3);
  v[0]=make_float2(v[0].x*INV128f, v[0].y*INV128f);
  v[1]=make_float2(a1.x*INV128f, a1.y*INV128f);
  v[2]=make_float2(a2.x*INV128f, a2.y*INV128f);
  v[3]=make_float2(a3.x*INV128f, a3.y*INV128f);
  float2 t0=c_add(v[0],v[2]), t1=c_sub(v[0],v[2]);
  float2 t2=c_add(v[1],v[3]), t3=c_sub(v[1],v[3]);
  float2 pi3 = make_float2(-t3.y, t3.x);
  v[0]=c_add(t0,t2); v[2]=c_sub(t0,t2);
  v[1]=c_add(t1,pi3); v[3]=c_sub(t1,pi3);
}

// ---------------------------------------------------------------------------
// init kernels
// ---------------------------------------------------------------------------
__global__ void k_initW(){
  int k = threadIdx.x;
  if (k < NXX){
    float s, c;
    sincospif(-(float)k/64.0f, &s, &c);
    d_W[k] = make_float2(c, s);
  }
}

__global__ __launch_bounds__(256) void k_prep(const float* __restrict__ x,
                                              const float* __restrict__ x1,
                                              const float* __restrict__ x3,
                                              const float* __restrict__ ix){
  int i = blockIdx.x*256 + threadIdx.x;
  d_xk[i] = make_float2(ix[i], ix[VOL+i]);
  d_rr[i] = make_float2(x[i]*x3[i], x[VOL+i]*x3[VOL+i]);
  #pragma unroll
  for (int r=0;r<NR;r++){
    float m0 = x1[(size_t)i*NR + r];
    float m1 = x1[(size_t)VOL*NR + (size_t)i*NR + r];
    d_m8[(size_t)r*VOL + i] = make_uchar2(m0 != 0.f, m1 != 0.f);
  }
}

__device__ __forceinline__ int kofp(int p){
  int l = p & 31, k2 = p >> 5;
  return k2 + 4*(int)(__brev((unsigned)l) >> 27);
}

__global__ __launch_bounds__(256) void k_prepSe(const float* __restrict__ smv){
  int r = blockIdx.y;
  int o = blockIdx.x*256 + threadIdx.x;
  int zp = o>>14, yp = (o>>7)&127, xp = o&127;
  int kx = kofp(xp), ky = kofp(yp), kz = kofp(zp);
  int i1 = (kx<<14) | (ky<<7) | kz;
  int i2 = (((128-kx)&127)<<14) | (((128-ky)&127)<<7) | ((128-kz)&127);
  d_Se[(size_t)r*VOL + o] = 0.5f*(smv[(size_t)r*VOL + i1] + smv[(size_t)r*VOL + i2]);
}

// ---------------------------------------------------------------------------
// fwd-z with transpose-out: in natural [x][y][z] -> out[f][zp][x][y].
// Optional spatial mask per radius f; optional fused p = r + beta*p update,
// with beta reduced in-block from parity-buffered rs partials.
// 512 threads: 16 warps x 2 lines.
// ---------------------------------------------------------------------------
__global__ __launch_bounds__(512) void k_fwdzT(const float2* __restrict__ in,
                                               const uchar2* __restrict__ mask,
                                               float2* __restrict__ out,
                                               int betaFlag, int par,
                                               const float2* __restrict__ rvec,
                                               float2* __restrict__ pwrite){
  __shared__ float2 sT[4096];
  __shared__ float2 smr[512];
  int tid=threadIdx.x, l=tid&31, w=tid>>5;
  int x=blockIdx.x, yt=blockIdx.y, f=blockIdx.z;
  Tw tw = load_tw(l);
  float b0=0.f, b1=0.f;
  if (betaFlag){
    int idx = tid & 255, half = tid >> 8;
    float vn = d_rsp[((par^1)<<9) + (half<<8) + idx];   // rs_new partials
    float vo = d_rsp[(par<<9)     + (half<<8) + idx];   // rs_old partials
    smr[tid] = make_float2(vn, vo);
    __syncthreads();
    for (int s=128; s>0; s>>=1){
      if (idx < s){
        float2 a = smr[tid], b = smr[tid+s];
        smr[tid] = make_float2(a.x+b.x, a.y+b.y);
      }
      __syncthreads();
    }
    float2 r0 = smr[0], r1 = smr[256];
    b0 = r0.x/(r0.y+EPSI);
    b1 = r1.x/(r1.y+EPSI);
    __syncthreads();
  }
  const uchar2* pm = mask ? (mask + (size_t)f*VOL) : (const uchar2*)0;
  #pragma unroll
  for (int ln=0; ln<2; ln++){
    int c=(w<<1)+ln;
    int y=(yt<<5)+c;
    size_t base=(size_t)x*16384 + (size_t)y*128;
    float2 v[4];
    #pragma unroll
    for (int k=0;k<4;k++){
      int z=l+(k<<5);
      float2 t=in[base+z];
      if (betaFlag){
        float2 rv=rvec[base+z];
        t=make_float2(rv.x+b0*t.x, rv.y+b1*t.y);
        pwrite[base+z]=t;
      }
      if (pm){ uchar2 m=pm[base+z]; t.x*=(float)m.x; t.y*=(float)m.y; }
      v[k]=t;
    }
    wf_fwd(v,tw,l);
    #pragma unroll
    for (int k=0;k<4;k++) sT[swz32(l+(k<<5), c)] = v[k];
  }
  __syncthreads();
  float2* po = out + (size_t)f*VOL + (size_t)x*128 + ((size_t)yt<<5);
  for (int i=tid;i<2048;i+=512){
    int zp=i>>4, c2=(i&15)<<1;
    float2 a = sT[swz32(zp,c2)];
    float2 b = sT[swz32(zp,c2|1)];
    *reinterpret_cast<float4*>(po + (size_t)zp*16384 + c2) = make_float4(a.x,a.y,b.x,b.y);
  }
}

// ---------------------------------------------------------------------------
// plane spread: per zp: fwd-y (global->regs), fwd-x (F in regs), per r:
// *Se_r, inv-x, inv-y (regs->global into tmp[r][zp][x][y]).
// 640 threads: 20 warps, 6 or 7 lines each.
// ---------------------------------------------------------------------------
__global__ __launch_bounds__(PTHREADS,1) void k_plane1(const float2* __restrict__ cin,
                                                       const float* __restrict__ Se,
                                                       float2* __restrict__ outT){
  extern __shared__ unsigned char smraw[];
  float2* sP = reinterpret_cast<float2*>(smraw);
  int tid=threadIdx.x, l=tid&31, w=tid>>5;   // 20 warps
  int cnt   = (w<12)? 6 : 7;
  int lbase = (w<12)? 6*w : 72 + 7*(w-12);
  int zp=blockIdx.x;
  Tw tw = load_tw(l);
  const float2* pin = cin + (size_t)zp*16384;
  #pragma unroll 7
  for (int j=0; j<7; j++){                   // fwd-y
    if (j>=cnt) break;
    int x=lbase+j;
    float2 v[4];
    #pragma unroll
    for (int k=0;k<4;k++) v[k]=pin[x*128 + l+(k<<5)];
    wf_fwd(v,tw,l);
    #pragma unroll
    for (int k=0;k<4;k++) sP[swz128(x, l+(k<<5))] = v[k];
  }
  __syncthreads();
  float2 F[7][4];
  #pragma unroll 7
  for (int j=0; j<7; j++){                   // fwd-x, keep F in regs
    if (j>=cnt) break;
    int yc=lbase+j;
    #pragma unroll
    for (int k=0;k<4;k++) F[j][k] = sP[swz128(l+(k<<5), yc)];
    wf_fwd(F[j],tw,l);
  }
  for (int r=0;r<NR;r++){
    __syncthreads();
    const float* pS = Se + (size_t)r*VOL + (size_t)zp*16384;
    #pragma unroll 7
    for (int j=0; j<7; j++){
      if (j>=cnt) break;
      int yc=lbase+j;
      float2 v[4];
      #pragma unroll
      for (int k=0;k<4;k++){
        float s=pS[yc*128 + l+(k<<5)];
        v[k]=make_float2(F[j][k].x*s, F[j][k].y*s);
      }
      wf_inv(v,tw,l);
      #pragma unroll
      for (int k=0;k<4;k++) sP[swz128(l+(k<<5), yc)] = v[k];
    }
    __syncthreads();
    float2* po = outT + (size_t)r*VOL + (size_t)zp*16384;
    #pragma unroll 7
    for (int j=0; j<7; j++){
      if (j>=cnt) break;
      int x=lbase+j;
      float2 v[4];
      #pragma unroll
      for (int k=0;k<4;k++) v[k] = sP[swz128(x, l+(k<<5))];
      wf_inv(v,tw,l);
      #pragma unroll
      for (int k=0;k<4;k++) po[x*128 + l+(k<<5)] = v[k];
    }
  }
}

// ---------------------------------------------------------------------------
// fused z on tmp[r]: inv-z, spatial mask, fwd-z (in-place, transposed layout).
// 512 threads: 16 warps x 2 lines.
// ---------------------------------------------------------------------------
__global__ __launch_bounds__(512) void k_zfuseT(float2* __restrict__ io,
                                                const uchar2* __restrict__ mask){
  __shared__ float2 sT[4096];
  int tid=threadIdx.x, l=tid&31, w=tid>>5;
  int x=blockIdx.x, yt=blockIdx.y, f=blockIdx.z;
  Tw tw = load_tw(l);
  float2* p0 = io + (size_t)f*VOL + (size_t)x*128 + ((size_t)yt<<5);
  for (int i=tid;i<2048;i+=512){
    int zp=i>>4, c2=(i&15)<<1;
    float4 v4 = *reinterpret_cast<const float4*>(p0 + (size_t)zp*16384 + c2);
    sT[swz32(zp,c2)]   = make_float2(v4.x, v4.y);
    sT[swz32(zp,c2|1)] = make_float2(v4.z, v4.w);
  }
  __syncthreads();
  const uchar2* pm = mask + (size_t)f*VOL;
  #pragma unroll
  for (int ln=0; ln<2; ln++){
    int c=(w<<1)+ln;
    int y=(yt<<5)+c;
    float2 v[4];
    #pragma unroll
    for (int k=0;k<4;k++) v[k] = sT[swz32(l+(k<<5), c)];
    wf_inv(v,tw,l);
    size_t base=(size_t)x*16384 + (size_t)y*128;
    #pragma unroll
    for (int k=0;k<4;k++){
      int z=l+(k<<5);
      uchar2 m=pm[base+z];
      v[k].x*=(float)m.x; v[k].y*=(float)m.y;
    }
    wf_fwd(v,tw,l);
    #pragma unroll
    for (int k=0;k<4;k++) sT[swz32(l+(k<<5), c)] = v[k];
  }
  __syncthreads();
  for (int i=tid;i<2048;i+=512){
    int zp=i>>4, c2=(i&15)<<1;
    float2 a = sT[swz32(zp,c2)];
    float2 b = sT[swz32(zp,c2|1)];
    *reinterpret_cast<float4*>(p0 + (size_t)zp*16384 + c2) = make_float4(a.x,a.y,b.x,b.y);
  }
}

// ---------------------------------------------------------------------------
// plane gather: per zp: for r: fwd-y, fwd-x, acc += Se*(.), then inv-x,
// inv-y (regs->global C0[zp][x][y]). 640 threads.
// ---------------------------------------------------------------------------
__global__ __launch_bounds__(PTHREADS,1) void k_plane2(const float2* __restrict__ tmp,
                                                       const float* __restrict__ Se,
                                                       float2* __restrict__ cout){
  extern __shared__ unsigned char smraw[];
  float2* sP = reinterpret_cast<float2*>(smraw);
  int tid=threadIdx.x, l=tid&31, w=tid>>5;
  int cnt   = (w<12)? 6 : 7;
  int lbase = (w<12)? 6*w : 72 + 7*(w-12);
  int zp=blockIdx.x;
  Tw tw = load_tw(l);
  float2 acc[7][4];
  #pragma unroll
  for (int a=0;a<7;a++)
    #pragma unroll
    for (int k=0;k<4;k++) acc[a][k]=make_float2(0.f,0.f);
  for (int r=0;r<NR;r++){
    const float2* pin = tmp + (size_t)r*VOL + (size_t)zp*16384;
    __syncthreads();
    #pragma unroll 7
    for (int j=0; j<7; j++){                // fwd-y
      if (j>=cnt) break;
      int x=lbase+j;
      float2 v[4];
      #pragma unroll
      for (int k=0;k<4;k++) v[k]=pin[x*128 + l+(k<<5)];
      wf_fwd(v,tw,l);
      #pragma unroll
      for (int k=0;k<4;k++) sP[swz128(x, l+(k<<5))] = v[k];
    }
    __syncthreads();
    const float* pS = Se + (size_t)r*VOL + (size_t)zp*16384;
    #pragma unroll 7
    for (int j=0; j<7; j++){                // fwd-x + accumulate
      if (j>=cnt) break;
      int yc=lbase+j;
      float2 v[4];
      #pragma unroll
      for (int k=0;k<4;k++) v[k] = sP[swz128(l+(k<<5), yc)];
      wf_fwd(v,tw,l);
      #pragma unroll
      for (int k=0;k<4;k++){
        float s=pS[yc*128 + l+(k<<5)];
        acc[j][k].x += v[k].x*s; acc[j][k].y += v[k].y*s;
      }
    }
  }
  __syncthreads();
  #pragma unroll 7
  for (int j=0; j<7; j++){                  // inv-x from acc
    if (j>=cnt) break;
    int yc=lbase+j;
    float2 v[4];
    #pragma unroll
    for (int k=0;k<4;k++) v[k]=acc[j][k];
    wf_inv(v,tw,l);
    #pragma unroll
    for (int k=0;k<4;k++) sP[swz128(l+(k<<5), yc)] = v[k];
  }
  __syncthreads();
  float2* po = cout + (size_t)zp*16384;
  #pragma unroll 7
  for (int j=0; j<7; j++){                  // inv-y -> global direct
    if (j>=cnt) break;
    int x=lbase+j;
    float2 v[4];
    #pragma unroll
    for (int k=0;k<4;k++) v[k] = sP[swz128(x, l+(k<<5))];
    wf_inv(v,tw,l);
    #pragma unroll
    for (int k=0;k<4;k++) po[x*128 + l+(k<<5)] = v[k];
  }
}

// ---------------------------------------------------------------------------
// inv-z from transposed -> natural Ap = (.) + lam*p, fused partial dot(p,Ap)
// 512 threads: 16 warps x 2 lines. partial index b = bx*4+by in [0,512).
// ---------------------------------------------------------------------------
__global__ __launch_bounds__(512) void k_invzT_ap(const float2* __restrict__ cin,
                                                  float2* __restrict__ outAp,
                                                  const float2* __restrict__ pvec,
                                                  float lam, float* __restrict__ part){
  __shared__ float2 sT[4096];
  __shared__ float sm0[512], sm1[512];
  int tid=threadIdx.x, l=tid&31, w=tid>>5;
  int x=blockIdx.x, yt=blockIdx.y;
  Tw tw = load_tw(l);
  const float2* p0 = cin + (size_t)x*128 + ((size_t)yt<<5);
  for (int i=tid;i<2048;i+=512){
    int zp=i>>4, c2=(i&15)<<1;
    float4 v4 = *reinterpret_cast<const float4*>(p0 + (size_t)zp*16384 + c2);
    sT[swz32(zp,c2)]   = make_float2(v4.x, v4.y);
    sT[swz32(zp,c2|1)] = make_float2(v4.z, v4.w);
  }
  __syncthreads();
  float s0=0.f, s1=0.f;
  #pragma unroll
  for (int ln=0; ln<2; ln++){
    int c=(w<<1)+ln, y=(yt<<5)+c;
    float2 v[4];
    #pragma unroll
    for (int k=0;k<4;k++) v[k] = sT[swz32(l+(k<<5), c)];
    wf_inv(v,tw,l);
    size_t base=(size_t)x*16384 + (size_t)y*128;
    #pragma unroll
    for (int k=0;k<4;k++){
      int z=l+(k<<5);
      float2 ap=v[k];
      if (pvec){
        float2 pv=pvec[base+z];
        ap.x+=lam*pv.x; ap.y+=lam*pv.y;
        s0+=pv.x*ap.x; s1+=pv.y*ap.y;
      }
      outAp[base+z]=ap;
    }
  }
  if (part){
    sm0[tid]=s0; sm1[tid]=s1; __syncthreads();
    for (int s=256;s>0;s>>=1){ if(tid<s){sm0[tid]+=sm0[tid+s];sm1[tid]+=sm1[tid+s];} __syncthreads(); }
    if (tid==0){ int b=blockIdx.x*4+blockIdx.y; part[b]=sm0[0]; part[1024+b]=sm1[0]; }
  }
}

// ---------------------------------------------------------------------------
// CG machinery: init_r writes rs partials to parity 1; update1 reduces
// rs (parity par^1) + pAp partials in-block, updates xk/r, writes rsn
// partials to parity par. No separate scalar kernels.
// ---------------------------------------------------------------------------
__global__ __launch_bounds__(256) void k_init_r(){
  __shared__ float sm0[256], sm1[256];
  int t = threadIdx.x;
  float s0=0.f, s1=0.f;
  for (int i=blockIdx.x*256+t; i<VOL; i+=256*256){
    float2 v = make_float2(d_bb[i].x - d_Ap[i].x, d_bb[i].y - d_Ap[i].y);
    d_rr[i]=v; d_pp[i]=v;
    s0 += v.x*v.x; s1 += v.y*v.y;
  }
  sm0[t]=s0; sm1[t]=s1; __syncthreads();
  for (int st=128; st>0; st>>=1){ if (t<st){ sm0[t]+=sm0[t+st]; sm1[t]+=sm1[t+st]; } __syncthreads(); }
  if (t==0){ d_rsp[512 + blockIdx.x]=sm0[0]; d_rsp[512 + 256 + blockIdx.x]=sm1[0]; }
}

__global__ __launch_bounds__(256) void k_update1(int par){
  __shared__ float4 smq[256];
  __shared__ float sm0[256], sm1[256];
  int t = threadIdx.x;
  {
    int rp = par^1;
    float rs0 = d_rsp[(rp<<9) + t];
    float rs1 = d_rsp[(rp<<9) + 256 + t];
    float pa0 = d_part[t] + d_part[256 + t];
    float pa1 = d_part[1024 + t] + d_part[1280 + t];
    smq[t] = make_float4(rs0, rs1, pa0, pa1);
  }
  __syncthreads();
  for (int st=128; st>0; st>>=1){
    if (t<st){
      float4 a = smq[t], b = smq[t+st];
      smq[t] = make_float4(a.x+b.x, a.y+b.y, a.z+b.z, a.w+b.w);
    }
    __syncthreads();
  }
  float4 tot = smq[0];
  float a0 = tot.x / (tot.z + EPSI);
  float a1 = tot.y / (tot.w + EPSI);
  float s0=0.f, s1=0.f;
  for (int i=blockIdx.x*256+t; i<VOL; i+=256*256){
    float2 p = d_pp[i], ap = d_Ap[i], xk = d_xk[i], r = d_rr[i];
    xk.x += a0*p.x;  xk.y += a1*p.y;  d_xk[i]=xk;
    r.x  -= a0*ap.x; r.y  -= a1*ap.y; d_rr[i]=r;
    s0 += r.x*r.x;   s1 += r.y*r.y;
  }
  sm0[t]=s0; sm1[t]=s1; __syncthreads();
  for (int st=128; st>0; st>>=1){ if (t<st){ sm0[t]+=sm0[t+st]; sm1[t]+=sm1[t+st]; } __syncthreads(); }
  if (t==0){ d_rsp[(par<<9) + blockIdx.x]=sm0[0]; d_rsp[(par<<9) + 256 + blockIdx.x]=sm1[0]; }
}

__global__ __launch_bounds__(256) void k_unpack(float* __restrict__ out){
  int i = blockIdx.x*256 + threadIdx.x;
  float2 v = d_xk[i];
  out[i] = v.x;
  out[VOL+i] = v.y;
}

// ---------------------------------------------------------------------------
// Host side
// ---------------------------------------------------------------------------
static void applyA(const float2* vin, float2* vout, float* pPart, int beta, int par,
                   float2* pC0, float2* pTmp, const float* pSe, const uchar2* pM8,
                   float2* pR, float2* pP){
  if (beta){
    k_fwdzT<<<dim3(128,4,1), 512>>>(pP, 0, pC0, 1, par, pR, pP);
  } else {
    k_fwdzT<<<dim3(128,4,1), 512>>>(vin, 0, pC0, 0, 0, 0, 0);
  }
  k_plane1 <<<128, PTHREADS, PLANE_SMEM>>>(pC0, pSe, pTmp);
  k_zfuseT <<<dim3(128,4,NR), 512>>>(pTmp, pM8);
  k_plane2 <<<128, PTHREADS, PLANE_SMEM>>>(pTmp, pSe, pC0);
  k_invzT_ap<<<dim3(128,4), 512>>>(pC0, vout, beta ? pP : vin, LAMBDA, pPart);
}

extern "C" void kernel_launch(void* const* d_in, const int* in_sizes, int n_in,
                              void* d_out, int out_size){
  const float* x      = (const float*)d_in[0];
  const float* x1     = (const float*)d_in[1];
  const float* x3     = (const float*)d_in[2];
  const float* init_x = (const float*)d_in[3];
  const float* smv    = (const float*)d_in[4];
  float* out = (float*)d_out;

  float2 *pC0, *pTmp, *pB, *pXk, *pR, *pP, *pAp;
  float *pSe, *pPart;
  uchar2 *pM8;
  cudaGetSymbolAddress((void**)&pC0,  d_C0);
  cudaGetSymbolAddress((void**)&pTmp, d_tmp);
  cudaGetSymbolAddress((void**)&pSe,  d_Se);
  cudaGetSymbolAddress((void**)&pM8,  d_m8);
  cudaGetSymbolAddress((void**)&pB,   d_bb);
  cudaGetSymbolAddress((void**)&pXk,  d_xk);
  cudaGetSymbolAddress((void**)&pR,   d_rr);
  cudaGetSymbolAddress((void**)&pP,   d_pp);
  cudaGetSymbolAddress((void**)&pAp,  d_Ap);
  cudaGetSymbolAddress((void**)&pPart,d_part);

  cudaFuncSetAttribute(k_plane1, cudaFuncAttributeMaxDynamicSharedMemorySize, PLANE_SMEM);
  cudaFuncSetAttribute(k_plane2, cudaFuncAttributeMaxDynamicSharedMemorySize, PLANE_SMEM);

  k_initW <<<1,128>>>();
  k_prep  <<<VOL/256, 256>>>(x, x1, x3, init_x);
  k_prepSe<<<dim3(VOL/256, NR), 256>>>(smv);

  // b = smv_adj( m * (w3*x) ); wx packed is in d_rr
  k_fwdzT  <<<dim3(128,4,NR), 512>>>(pR, pM8, pTmp, 0, 0, 0, 0);
  k_plane2 <<<128, PTHREADS, PLANE_SMEM>>>(pTmp, pSe, pC0);
  k_invzT_ap<<<dim3(128,4), 512>>>(pC0, pB, 0, 0.f, 0);

  // r0 = b - A(x0); p = r0; rs partials -> parity 1
  applyA(pXk, pAp, 0, 0, 0, pC0, pTmp, pSe, pM8, pR, pP);
  k_init_r<<<256, 256>>>();

  for (int it=0; it<NITER; ++it){
    applyA(pP, pAp, pPart, (it>0)?1:0, it&1, pC0, pTmp, pSe, pM8, pR, pP);
    k_update1<<<256, 256>>>(it&1);
  }

  k_unpack<<<VOL/256, 256>>>(out);
}